// round 1
// baseline (speedup 1.0000x reference)
#include <cuda_runtime.h>

// Problem constants
#define C_DIM 1024
#define B_DIM 4
#define T_DIM 2048
#define H_DIM 16
#define HD    64
#define M_TOT (B_DIM * T_DIM)   // 8192
#define N_TOT (3 * C_DIM)       // 3072

// Scratch for Q/K/V in [B,H,T,D] layout (no cudaMalloc allowed)
__device__ float g_q[(size_t)M_TOT * C_DIM];
__device__ float g_k[(size_t)M_TOT * C_DIM];
__device__ float g_v[(size_t)M_TOT * C_DIM];

// ---------------------------------------------------------------------------
// QKV GEMM: qkv[m, o] = sum_c x[m,c] * W[o,c] + b[o]
// Scatters result directly into g_q/g_k/g_v in [B,H,T,D] layout.
// Tile: 64x64x16, 256 threads, 4x4 microtile per thread.
// ---------------------------------------------------------------------------
__global__ __launch_bounds__(256) void qkv_gemm_kernel(
    const float* __restrict__ x,
    const float* __restrict__ W,
    const float* __restrict__ b)
{
    __shared__ float As[64][17];
    __shared__ float Bs[64][17];

    const int tid = threadIdx.x;
    const int tx = tid & 15;       // 0..15 -> N microtile
    const int ty = tid >> 4;       // 0..15 -> M microtile
    const int m0 = blockIdx.y * 64;
    const int n0 = blockIdx.x * 64;

    const int lrow = tid >> 2;         // 0..63
    const int lk   = (tid & 3) * 4;    // 0,4,8,12

    const float* aptr = x + (size_t)(m0 + lrow) * C_DIM + lk;
    const float* bptr = W + (size_t)(n0 + lrow) * C_DIM + lk;

    float acc[4][4] = {};

    for (int k0 = 0; k0 < C_DIM; k0 += 16) {
        float4 av = *(const float4*)(aptr + k0);
        float4 bv = *(const float4*)(bptr + k0);
        __syncthreads();   // previous compute done before overwrite
        As[lrow][lk + 0] = av.x; As[lrow][lk + 1] = av.y;
        As[lrow][lk + 2] = av.z; As[lrow][lk + 3] = av.w;
        Bs[lrow][lk + 0] = bv.x; Bs[lrow][lk + 1] = bv.y;
        Bs[lrow][lk + 2] = bv.z; Bs[lrow][lk + 3] = bv.w;
        __syncthreads();

        #pragma unroll
        for (int k = 0; k < 16; k++) {
            float a[4], bb[4];
            #pragma unroll
            for (int i = 0; i < 4; i++) a[i]  = As[ty * 4 + i][k];
            #pragma unroll
            for (int j = 0; j < 4; j++) bb[j] = Bs[tx * 4 + j][k];
            #pragma unroll
            for (int i = 0; i < 4; i++)
                #pragma unroll
                for (int j = 0; j < 4; j++)
                    acc[i][j] += a[i] * bb[j];
        }
    }

    // Epilogue: bias + scatter. Tile (n0..n0+63) lies entirely within one
    // (which, head) pair since D=64 and tiles are 64-aligned.
    const int which = n0 / C_DIM;
    const int h     = (n0 % C_DIM) / HD;
    float* dst = (which == 0) ? g_q : (which == 1) ? g_k : g_v;
    const int bq = m0 / T_DIM;
    const int t0 = m0 % T_DIM;

    float4 bias = *(const float4*)(b + n0 + tx * 4);

    #pragma unroll
    for (int i = 0; i < 4; i++) {
        const int t = t0 + ty * 4 + i;
        float4 o;
        o.x = acc[i][0] + bias.x;
        o.y = acc[i][1] + bias.y;
        o.z = acc[i][2] + bias.z;
        o.w = acc[i][3] + bias.w;
        *(float4*)(dst + (((size_t)(bq * H_DIM + h) * T_DIM + t) * HD) + tx * 4) = o;
    }
}

// ---------------------------------------------------------------------------
// Flash-attention style causal attention.
// grid = (32 q-tiles, 64 batch*head), 256 threads.
// Dynamic smem: Qs/Ks/Vs/Ss 64x65 fp32 tiles + row stats.
// ---------------------------------------------------------------------------
#define SMEM_FLOATS (4 * 64 * 65 + 3 * 64)
#define SMEM_BYTES  (SMEM_FLOATS * 4)

__global__ __launch_bounds__(256) void attn_kernel(float* __restrict__ out)
{
    extern __shared__ float sm[];
    float (*Qs)[65] = (float(*)[65])(sm);
    float (*Ks)[65] = (float(*)[65])(sm + 64 * 65);
    float (*Vs)[65] = (float(*)[65])(sm + 2 * 64 * 65);
    float (*Ss)[65] = (float(*)[65])(sm + 3 * 64 * 65);
    float* mrow = sm + 4 * 64 * 65;
    float* lsum = mrow + 64;
    float* crow = lsum + 64;

    const int tid = threadIdx.x;
    const int tx = tid & 15;
    const int ty = tid >> 4;
    const int qt = blockIdx.x;   // q tile 0..31
    const int bh = blockIdx.y;   // batch*head 0..63

    const size_t hoff = (size_t)bh * T_DIM * HD;
    const float* Q = g_q + hoff;
    const float* K = g_k + hoff;
    const float* V = g_v + hoff;

    const int lrow = tid >> 2;           // 0..63
    const int lc0  = (tid & 3) * 16;     // 0,16,32,48

    // Load Q tile, pre-scaled by 1/sqrt(D) = 0.125
    {
        const float* qp = Q + (size_t)(qt * 64 + lrow) * HD + lc0;
        #pragma unroll
        for (int v = 0; v < 4; v++) {
            float4 q4 = *(const float4*)(qp + v * 4);
            Qs[lrow][lc0 + v * 4 + 0] = q4.x * 0.125f;
            Qs[lrow][lc0 + v * 4 + 1] = q4.y * 0.125f;
            Qs[lrow][lc0 + v * 4 + 2] = q4.z * 0.125f;
            Qs[lrow][lc0 + v * 4 + 3] = q4.w * 0.125f;
        }
    }
    if (tid < 64) { mrow[tid] = -1e30f; lsum[tid] = 0.0f; }

    float oacc[4][4] = {};

    for (int kt = 0; kt <= qt; kt++) {
        __syncthreads();   // all readers of Ks/Vs/Ss from prev iter done
        {
            const float* kp = K + (size_t)(kt * 64 + lrow) * HD + lc0;
            const float* vp = V + (size_t)(kt * 64 + lrow) * HD + lc0;
            #pragma unroll
            for (int v = 0; v < 4; v++) {
                float4 k4 = *(const float4*)(kp + v * 4);
                Ks[lrow][lc0 + v * 4 + 0] = k4.x;
                Ks[lrow][lc0 + v * 4 + 1] = k4.y;
                Ks[lrow][lc0 + v * 4 + 2] = k4.z;
                Ks[lrow][lc0 + v * 4 + 3] = k4.w;
                float4 v4 = *(const float4*)(vp + v * 4);
                Vs[lrow][lc0 + v * 4 + 0] = v4.x;
                Vs[lrow][lc0 + v * 4 + 1] = v4.y;
                Vs[lrow][lc0 + v * 4 + 2] = v4.z;
                Vs[lrow][lc0 + v * 4 + 3] = v4.w;
            }
        }
        __syncthreads();

        // S = (Q*scale) @ K^T
        float s[4][4] = {};
        #pragma unroll 4
        for (int d = 0; d < HD; d++) {
            float a[4], bb[4];
            #pragma unroll
            for (int i = 0; i < 4; i++) a[i]  = Qs[ty * 4 + i][d];
            #pragma unroll
            for (int j = 0; j < 4; j++) bb[j] = Ks[tx * 4 + j][d];
            #pragma unroll
            for (int i = 0; i < 4; i++)
                #pragma unroll
                for (int j = 0; j < 4; j++)
                    s[i][j] += a[i] * bb[j];
        }

        const bool diag = (kt == qt);
        #pragma unroll
        for (int i = 0; i < 4; i++) {
            const int r = ty * 4 + i;
            #pragma unroll
            for (int j = 0; j < 4; j++) {
                const int c = tx * 4 + j;
                float val = s[i][j];
                if (diag && c > r) val = -1e30f;
                Ss[r][c] = val;
            }
        }
        __syncthreads();

        // Online softmax: one thread per row
        if (tid < 64) {
            const int r = tid;
            float mold = mrow[r];
            float mx = mold;
            #pragma unroll 8
            for (int c = 0; c < 64; c++) mx = fmaxf(mx, Ss[r][c]);
            float corr = __expf(mold - mx);
            float sum = 0.0f;
            #pragma unroll 8
            for (int c = 0; c < 64; c++) {
                float p = __expf(Ss[r][c] - mx);
                Ss[r][c] = p;
                sum += p;
            }
            mrow[r] = mx;
            lsum[r] = lsum[r] * corr + sum;
            crow[r] = corr;
        }
        __syncthreads();

        // O = O * corr + P @ V
        float cr[4];
        #pragma unroll
        for (int i = 0; i < 4; i++) cr[i] = crow[ty * 4 + i];
        #pragma unroll
        for (int i = 0; i < 4; i++)
            #pragma unroll
            for (int j = 0; j < 4; j++)
                oacc[i][j] *= cr[i];

        #pragma unroll 4
        for (int s2 = 0; s2 < 64; s2++) {
            float a[4], bb[4];
            #pragma unroll
            for (int i = 0; i < 4; i++) a[i]  = Ss[ty * 4 + i][s2];
            #pragma unroll
            for (int j = 0; j < 4; j++) bb[j] = Vs[s2][tx * 4 + j];
            #pragma unroll
            for (int i = 0; i < 4; i++)
                #pragma unroll
                for (int j = 0; j < 4; j++)
                    oacc[i][j] += a[i] * bb[j];
        }
    }

    // Write O / l back to [B, T, C] layout
    const int bq = bh >> 4;
    const int h  = bh & 15;
    #pragma unroll
    for (int i = 0; i < 4; i++) {
        const int r = ty * 4 + i;
        const float inv = 1.0f / lsum[r];
        const int t = qt * 64 + r;
        float4 o;
        o.x = oacc[i][0] * inv;
        o.y = oacc[i][1] * inv;
        o.z = oacc[i][2] * inv;
        o.w = oacc[i][3] * inv;
        *(float4*)(out + ((size_t)(bq * T_DIM + t) * C_DIM) + h * HD + tx * 4) = o;
    }
}

// ---------------------------------------------------------------------------
extern "C" void kernel_launch(void* const* d_in, const int* in_sizes, int n_in,
                              void* d_out, int out_size)
{
    const float* x = (const float*)d_in[0];   // [4, 2048, 1024]
    const float* W = (const float*)d_in[1];   // [3072, 1024]
    const float* b = (const float*)d_in[2];   // [3072]
    float* out = (float*)d_out;               // [4, 2048, 1024]

    cudaFuncSetAttribute(attn_kernel, cudaFuncAttributeMaxDynamicSharedMemorySize,
                         SMEM_BYTES);

    qkv_gemm_kernel<<<dim3(N_TOT / 64, M_TOT / 64), 256>>>(x, W, b);
    attn_kernel<<<dim3(T_DIM / 64, B_DIM * H_DIM), 256, SMEM_BYTES>>>(out);
}

// round 2
// speedup vs baseline: 2.6157x; 2.6157x over previous
#include <cuda_runtime.h>
#include <cstdint>

#define C_DIM 1024
#define B_DIM 4
#define T_DIM 2048
#define H_DIM 16
#define HD    64
#define M_TOT (B_DIM * T_DIM)   // 8192
#define N_TOT (3 * C_DIM)       // 3072

// Q/K/V scratch in [B,H,T,D] layout
__device__ float g_q[(size_t)M_TOT * C_DIM];
__device__ float g_k[(size_t)M_TOT * C_DIM];
__device__ float g_v[(size_t)M_TOT * C_DIM];

__device__ __forceinline__ uint32_t f2tf(float f) {
    uint32_t u;
    asm("cvt.rna.tf32.f32 %0, %1;" : "=r"(u) : "f"(f));
    return u;
}

__device__ __forceinline__ void mma_tf32(float c[4], const uint32_t a[4],
                                         const uint32_t b[2]) {
    asm volatile(
        "mma.sync.aligned.m16n8k8.row.col.f32.tf32.tf32.f32 "
        "{%0,%1,%2,%3}, {%4,%5,%6,%7}, {%8,%9}, {%0,%1,%2,%3};"
        : "+f"(c[0]), "+f"(c[1]), "+f"(c[2]), "+f"(c[3])
        : "r"(a[0]), "r"(a[1]), "r"(a[2]), "r"(a[3]), "r"(b[0]), "r"(b[1]));
}

// ---------------------------------------------------------------------------
// QKV GEMM (TF32 tensor cores): qkv[m,o] = x[m,:] . W[o,:] + b[o]
// CTA tile 128x128, k-tile 16, 8 warps (2M x 4N), warp tile 64x32.
// Scatters into g_q/g_k/g_v in [B,H,T,D].
// ---------------------------------------------------------------------------
__global__ __launch_bounds__(256) void qkv_gemm_tf32(
    const float* __restrict__ x,
    const float* __restrict__ W,
    const float* __restrict__ b)
{
    __shared__ uint32_t As[128][20];   // pad 20: bank = (4*row'+col')%32, conflict-free
    __shared__ uint32_t Bs[128][20];

    const int tid  = threadIdx.x;
    const int lane = tid & 31;
    const int warp = tid >> 5;
    const int wm = warp >> 2;          // 0..1
    const int wn = warp & 3;           // 0..3
    const int m0 = blockIdx.y * 128;
    const int n0 = blockIdx.x * 128;

    const int lrow = tid >> 1;             // 0..127
    const int lcol = (tid & 1) * 8;        // 0 or 8
    const float* ap = x + (size_t)(m0 + lrow) * C_DIM + lcol;
    const float* bp = W + (size_t)(n0 + lrow) * C_DIM + lcol;

    float acc[4][4][4] = {};

    for (int k0 = 0; k0 < C_DIM; k0 += 16) {
        float4 av0 = *(const float4*)(ap + k0);
        float4 av1 = *(const float4*)(ap + k0 + 4);
        float4 bv0 = *(const float4*)(bp + k0);
        float4 bv1 = *(const float4*)(bp + k0 + 4);
        __syncthreads();
        As[lrow][lcol + 0] = f2tf(av0.x); As[lrow][lcol + 1] = f2tf(av0.y);
        As[lrow][lcol + 2] = f2tf(av0.z); As[lrow][lcol + 3] = f2tf(av0.w);
        As[lrow][lcol + 4] = f2tf(av1.x); As[lrow][lcol + 5] = f2tf(av1.y);
        As[lrow][lcol + 6] = f2tf(av1.z); As[lrow][lcol + 7] = f2tf(av1.w);
        Bs[lrow][lcol + 0] = f2tf(bv0.x); Bs[lrow][lcol + 1] = f2tf(bv0.y);
        Bs[lrow][lcol + 2] = f2tf(bv0.z); Bs[lrow][lcol + 3] = f2tf(bv0.w);
        Bs[lrow][lcol + 4] = f2tf(bv1.x); Bs[lrow][lcol + 5] = f2tf(bv1.y);
        Bs[lrow][lcol + 6] = f2tf(bv1.z); Bs[lrow][lcol + 7] = f2tf(bv1.w);
        __syncthreads();

        #pragma unroll
        for (int ks = 0; ks < 16; ks += 8) {
            uint32_t af[4][4];
            #pragma unroll
            for (int mt = 0; mt < 4; mt++) {
                const int r = wm * 64 + mt * 16 + (lane >> 2);
                const int c = ks + (lane & 3);
                af[mt][0] = As[r][c];     af[mt][1] = As[r + 8][c];
                af[mt][2] = As[r][c + 4]; af[mt][3] = As[r + 8][c + 4];
            }
            uint32_t bf[4][2];
            #pragma unroll
            for (int nt = 0; nt < 4; nt++) {
                const int r = wn * 32 + nt * 8 + (lane >> 2);
                const int c = ks + (lane & 3);
                bf[nt][0] = Bs[r][c];
                bf[nt][1] = Bs[r][c + 4];
            }
            #pragma unroll
            for (int mt = 0; mt < 4; mt++)
                #pragma unroll
                for (int nt = 0; nt < 4; nt++)
                    mma_tf32(acc[mt][nt], af[mt], bf[nt]);
        }
    }

    // Epilogue: bias + scatter to [B,H,T,D]
    const int which = n0 >> 10;                 // tile never straddles q/k/v
    float* dst = (which == 0) ? g_q : (which == 1) ? g_k : g_v;
    const int bq = m0 >> 11;
    const int t0 = m0 & (T_DIM - 1);
    const int h  = (((n0 & 1023) + wn * 32) >> 6);  // constant per warp

    #pragma unroll
    for (int nt = 0; nt < 4; nt++) {
        const int ncol = wn * 32 + nt * 8 + 2 * (lane & 3);
        const float2 bias = *(const float2*)(b + n0 + ncol);
        const int d = ncol & 63;
        const size_t rowbase = (size_t)(bq * H_DIM + h) * T_DIM;
        #pragma unroll
        for (int mt = 0; mt < 4; mt++) {
            const int t = t0 + wm * 64 + mt * 16 + (lane >> 2);
            float2 v0 = { acc[mt][nt][0] + bias.x, acc[mt][nt][1] + bias.y };
            float2 v1 = { acc[mt][nt][2] + bias.x, acc[mt][nt][3] + bias.y };
            *(float2*)(dst + (rowbase + t) * HD + d)       = v0;
            *(float2*)(dst + (rowbase + t + 8) * HD + d)   = v1;
        }
    }
}

// ---------------------------------------------------------------------------
// Flash attention (TF32 tensor cores).
// CTA: 64 q-rows, 4 warps (16 rows each). KV tiles of 64.
// Online softmax fully in registers (quad shuffles).
// ---------------------------------------------------------------------------
#define KS_PAD 68   // bank = (4*row'+col')%32 for frag reads: conflict-free
#define VS_PAD 72   // bank = (8*row'+col')%32 for frag reads: conflict-free
#define SMEM_U32 (64 * KS_PAD + 64 * VS_PAD + 64 * KS_PAD)
#define ATTN_SMEM_BYTES (SMEM_U32 * 4)

__global__ __launch_bounds__(128) void attn_tf32(float* __restrict__ out)
{
    extern __shared__ uint32_t sm[];
    uint32_t (*Ks)[KS_PAD] = (uint32_t(*)[KS_PAD])(sm);
    uint32_t (*Vs)[VS_PAD] = (uint32_t(*)[VS_PAD])(sm + 64 * KS_PAD);
    uint32_t (*Ps)[KS_PAD] = (uint32_t(*)[KS_PAD])(sm + 64 * KS_PAD + 64 * VS_PAD);

    const int tid  = threadIdx.x;
    const int lane = tid & 31;
    const int warp = tid >> 5;
    const int qt = blockIdx.x;      // q tile 0..31
    const int bh = blockIdx.y;      // 0..63

    const size_t hoff = (size_t)bh * T_DIM * HD;
    const float* Qg = g_q + hoff;
    const float* Kg = g_k + hoff;
    const float* Vg = g_v + hoff;

    // Stage Q tile (scaled by 1/8) through Ps, then pull A-frags to registers.
    {
        const int row = tid >> 1;
        const int col = (tid & 1) * 32;
        const float* qp = Qg + (size_t)(qt * 64 + row) * HD + col;
        #pragma unroll
        for (int i = 0; i < 8; i++) {
            float4 v = *(const float4*)(qp + i * 4);
            Ps[row][col + i * 4 + 0] = f2tf(v.x * 0.125f);
            Ps[row][col + i * 4 + 1] = f2tf(v.y * 0.125f);
            Ps[row][col + i * 4 + 2] = f2tf(v.z * 0.125f);
            Ps[row][col + i * 4 + 3] = f2tf(v.w * 0.125f);
        }
    }
    __syncthreads();
    uint32_t qa[8][4];
    {
        const int r = warp * 16 + (lane >> 2);
        #pragma unroll
        for (int k = 0; k < 8; k++) {
            const int c = k * 8 + (lane & 3);
            qa[k][0] = Ps[r][c];     qa[k][1] = Ps[r + 8][c];
            qa[k][2] = Ps[r][c + 4]; qa[k][3] = Ps[r + 8][c + 4];
        }
    }

    float oa[8][4] = {};
    float mrow0 = -1e30f, mrow1 = -1e30f, l0 = 0.0f, l1 = 0.0f;
    const int gr0 = qt * 64 + warp * 16 + (lane >> 2);
    const int gr1 = gr0 + 8;

    for (int kt = 0; kt <= qt; kt++) {
        __syncthreads();  // Ks/Vs consumers from previous iter done, qa loads done
        {
            const int row = tid >> 1;
            const int col = (tid & 1) * 32;
            const float* kp = Kg + (size_t)(kt * 64 + row) * HD + col;
            const float* vp = Vg + (size_t)(kt * 64 + row) * HD + col;
            #pragma unroll
            for (int i = 0; i < 8; i++) {
                float4 kv = *(const float4*)(kp + i * 4);
                Ks[row][col + i * 4 + 0] = f2tf(kv.x);
                Ks[row][col + i * 4 + 1] = f2tf(kv.y);
                Ks[row][col + i * 4 + 2] = f2tf(kv.z);
                Ks[row][col + i * 4 + 3] = f2tf(kv.w);
                float4 vv = *(const float4*)(vp + i * 4);
                Vs[row][col + i * 4 + 0] = f2tf(vv.x);
                Vs[row][col + i * 4 + 1] = f2tf(vv.y);
                Vs[row][col + i * 4 + 2] = f2tf(vv.z);
                Vs[row][col + i * 4 + 3] = f2tf(vv.w);
            }
        }
        __syncthreads();

        // S = Q @ K^T
        float s[8][4] = {};
        #pragma unroll
        for (int k = 0; k < 8; k++) {
            #pragma unroll
            for (int j = 0; j < 8; j++) {
                uint32_t bfr[2];
                const int rr = j * 8 + (lane >> 2);
                const int cc = k * 8 + (lane & 3);
                bfr[0] = Ks[rr][cc];
                bfr[1] = Ks[rr][cc + 4];
                mma_tf32(s[j], qa[k], bfr);
            }
        }

        // Causal mask (diagonal tile only)
        if (kt == qt) {
            #pragma unroll
            for (int j = 0; j < 8; j++) {
                const int c0 = kt * 64 + j * 8 + 2 * (lane & 3);
                if (c0     > gr0) s[j][0] = -1e30f;
                if (c0 + 1 > gr0) s[j][1] = -1e30f;
                if (c0     > gr1) s[j][2] = -1e30f;
                if (c0 + 1 > gr1) s[j][3] = -1e30f;
            }
        }

        // Online softmax in registers (quad = lanes sharing lane>>2)
        float mx0 = -1e30f, mx1 = -1e30f;
        #pragma unroll
        for (int j = 0; j < 8; j++) {
            mx0 = fmaxf(mx0, fmaxf(s[j][0], s[j][1]));
            mx1 = fmaxf(mx1, fmaxf(s[j][2], s[j][3]));
        }
        mx0 = fmaxf(mx0, __shfl_xor_sync(0xffffffff, mx0, 1));
        mx0 = fmaxf(mx0, __shfl_xor_sync(0xffffffff, mx0, 2));
        mx1 = fmaxf(mx1, __shfl_xor_sync(0xffffffff, mx1, 1));
        mx1 = fmaxf(mx1, __shfl_xor_sync(0xffffffff, mx1, 2));

        const float nm0 = fmaxf(mrow0, mx0);
        const float nm1 = fmaxf(mrow1, mx1);
        const float corr0 = __expf(mrow0 - nm0);
        const float corr1 = __expf(mrow1 - nm1);
        mrow0 = nm0; mrow1 = nm1;

        float sum0 = 0.0f, sum1 = 0.0f;
        #pragma unroll
        for (int j = 0; j < 8; j++) {
            s[j][0] = __expf(s[j][0] - nm0); sum0 += s[j][0];
            s[j][1] = __expf(s[j][1] - nm0); sum0 += s[j][1];
            s[j][2] = __expf(s[j][2] - nm1); sum1 += s[j][2];
            s[j][3] = __expf(s[j][3] - nm1); sum1 += s[j][3];
        }
        sum0 += __shfl_xor_sync(0xffffffff, sum0, 1);
        sum0 += __shfl_xor_sync(0xffffffff, sum0, 2);
        sum1 += __shfl_xor_sync(0xffffffff, sum1, 1);
        sum1 += __shfl_xor_sync(0xffffffff, sum1, 2);
        l0 = l0 * corr0 + sum0;
        l1 = l1 * corr1 + sum1;

        #pragma unroll
        for (int j = 0; j < 8; j++) {
            oa[j][0] *= corr0; oa[j][1] *= corr0;
            oa[j][2] *= corr1; oa[j][3] *= corr1;
        }

        // Store P (warp-private rows of Ps)
        {
            const int r = warp * 16 + (lane >> 2);
            #pragma unroll
            for (int j = 0; j < 8; j++) {
                const int c = j * 8 + 2 * (lane & 3);
                Ps[r][c]         = f2tf(s[j][0]);
                Ps[r][c + 1]     = f2tf(s[j][1]);
                Ps[r + 8][c]     = f2tf(s[j][2]);
                Ps[r + 8][c + 1] = f2tf(s[j][3]);
            }
        }
        __syncwarp();

        // O += P @ V
        #pragma unroll
        for (int k2 = 0; k2 < 8; k2++) {
            uint32_t af[4];
            const int r = warp * 16 + (lane >> 2);
            const int c = k2 * 8 + (lane & 3);
            af[0] = Ps[r][c];     af[1] = Ps[r + 8][c];
            af[2] = Ps[r][c + 4]; af[3] = Ps[r + 8][c + 4];
            #pragma unroll
            for (int j = 0; j < 8; j++) {
                uint32_t bfr[2];
                const int vr = k2 * 8 + (lane & 3);
                const int vc = j * 8 + (lane >> 2);
                bfr[0] = Vs[vr][vc];
                bfr[1] = Vs[vr + 4][vc];
                mma_tf32(oa[j], af, bfr);
            }
        }
    }

    // Epilogue: normalize and write [B,T,C]
    const float inv0 = 1.0f / l0;
    const float inv1 = 1.0f / l1;
    const int bq = bh >> 4;
    const int h  = bh & 15;
    const int trow = qt * 64 + warp * 16 + (lane >> 2);
    #pragma unroll
    for (int j = 0; j < 8; j++) {
        const int d = j * 8 + 2 * (lane & 3);
        float2 v0 = { oa[j][0] * inv0, oa[j][1] * inv0 };
        float2 v1 = { oa[j][2] * inv1, oa[j][3] * inv1 };
        *(float2*)(out + (size_t)(bq * T_DIM + trow) * C_DIM + h * HD + d)     = v0;
        *(float2*)(out + (size_t)(bq * T_DIM + trow + 8) * C_DIM + h * HD + d) = v1;
    }
}

// ---------------------------------------------------------------------------
extern "C" void kernel_launch(void* const* d_in, const int* in_sizes, int n_in,
                              void* d_out, int out_size)
{
    const float* x = (const float*)d_in[0];   // [4, 2048, 1024]
    const float* W = (const float*)d_in[1];   // [3072, 1024]
    const float* b = (const float*)d_in[2];   // [3072]
    float* out = (float*)d_out;               // [4, 2048, 1024]

    cudaFuncSetAttribute(attn_tf32, cudaFuncAttributeMaxDynamicSharedMemorySize,
                         ATTN_SMEM_BYTES);

    qkv_gemm_tf32<<<dim3(N_TOT / 128, M_TOT / 128), 256>>>(x, W, b);
    attn_tf32<<<dim3(T_DIM / 64, B_DIM * H_DIM), 128, ATTN_SMEM_BYTES>>>(out);
}

// round 3
// speedup vs baseline: 2.6159x; 1.0001x over previous
#include <cuda_runtime.h>
#include <cstdint>

#define C_DIM 1024
#define B_DIM 4
#define T_DIM 2048
#define H_DIM 16
#define HD    64
#define M_TOT (B_DIM * T_DIM)   // 8192
#define N_TOT (3 * C_DIM)       // 3072

// Q/K/V scratch in [B,H,T,D] layout
__device__ float g_q[(size_t)M_TOT * C_DIM];
__device__ float g_k[(size_t)M_TOT * C_DIM];
__device__ float g_v[(size_t)M_TOT * C_DIM];

__device__ __forceinline__ uint32_t f2tf(float f) {
    uint32_t u;
    asm("cvt.rna.tf32.f32 %0, %1;" : "=r"(u) : "f"(f));
    return u;
}

__device__ __forceinline__ void mma_tf32(float c[4], const uint32_t a[4],
                                         const uint32_t b[2]) {
    asm volatile(
        "mma.sync.aligned.m16n8k8.row.col.f32.tf32.tf32.f32 "
        "{%0,%1,%2,%3}, {%4,%5,%6,%7}, {%8,%9}, {%0,%1,%2,%3};"
        : "+f"(c[0]), "+f"(c[1]), "+f"(c[2]), "+f"(c[3])
        : "r"(a[0]), "r"(a[1]), "r"(a[2]), "r"(a[3]), "r"(b[0]), "r"(b[1]));
}

// ---------------------------------------------------------------------------
// QKV GEMM (TF32 tensor cores): qkv[m,o] = x[m,:] . W[o,:] + b[o]
// CTA tile 128x128, k-tile 16, 8 warps (2M x 4N), warp tile 64x32.
// Scatters into g_q/g_k/g_v in [B,H,T,D].
// ---------------------------------------------------------------------------
__global__ __launch_bounds__(256) void qkv_gemm_tf32(
    const float* __restrict__ x,
    const float* __restrict__ W,
    const float* __restrict__ b)
{
    __shared__ uint32_t As[128][20];   // pad 20: bank = (4*row'+col')%32, conflict-free
    __shared__ uint32_t Bs[128][20];

    const int tid  = threadIdx.x;
    const int lane = tid & 31;
    const int warp = tid >> 5;
    const int wm = warp >> 2;          // 0..1
    const int wn = warp & 3;           // 0..3
    const int m0 = blockIdx.y * 128;
    const int n0 = blockIdx.x * 128;

    const int lrow = tid >> 1;             // 0..127
    const int lcol = (tid & 1) * 8;        // 0 or 8
    const float* ap = x + (size_t)(m0 + lrow) * C_DIM + lcol;
    const float* bp = W + (size_t)(n0 + lrow) * C_DIM + lcol;

    float acc[4][4][4] = {};

    for (int k0 = 0; k0 < C_DIM; k0 += 16) {
        float4 av0 = *(const float4*)(ap + k0);
        float4 av1 = *(const float4*)(ap + k0 + 4);
        float4 bv0 = *(const float4*)(bp + k0);
        float4 bv1 = *(const float4*)(bp + k0 + 4);
        __syncthreads();
        As[lrow][lcol + 0] = f2tf(av0.x); As[lrow][lcol + 1] = f2tf(av0.y);
        As[lrow][lcol + 2] = f2tf(av0.z); As[lrow][lcol + 3] = f2tf(av0.w);
        As[lrow][lcol + 4] = f2tf(av1.x); As[lrow][lcol + 5] = f2tf(av1.y);
        As[lrow][lcol + 6] = f2tf(av1.z); As[lrow][lcol + 7] = f2tf(av1.w);
        Bs[lrow][lcol + 0] = f2tf(bv0.x); Bs[lrow][lcol + 1] = f2tf(bv0.y);
        Bs[lrow][lcol + 2] = f2tf(bv0.z); Bs[lrow][lcol + 3] = f2tf(bv0.w);
        Bs[lrow][lcol + 4] = f2tf(bv1.x); Bs[lrow][lcol + 5] = f2tf(bv1.y);
        Bs[lrow][lcol + 6] = f2tf(bv1.z); Bs[lrow][lcol + 7] = f2tf(bv1.w);
        __syncthreads();

        #pragma unroll
        for (int ks = 0; ks < 16; ks += 8) {
            uint32_t af[4][4];
            #pragma unroll
            for (int mt = 0; mt < 4; mt++) {
                const int r = wm * 64 + mt * 16 + (lane >> 2);
                const int c = ks + (lane & 3);
                af[mt][0] = As[r][c];     af[mt][1] = As[r + 8][c];
                af[mt][2] = As[r][c + 4]; af[mt][3] = As[r + 8][c + 4];
            }
            uint32_t bf[4][2];
            #pragma unroll
            for (int nt = 0; nt < 4; nt++) {
                const int r = wn * 32 + nt * 8 + (lane >> 2);
                const int c = ks + (lane & 3);
                bf[nt][0] = Bs[r][c];
                bf[nt][1] = Bs[r][c + 4];
            }
            #pragma unroll
            for (int mt = 0; mt < 4; mt++)
                #pragma unroll
                for (int nt = 0; nt < 4; nt++)
                    mma_tf32(acc[mt][nt], af[mt], bf[nt]);
        }
    }

    // Epilogue: bias + scatter to [B,H,T,D]
    const int which = n0 >> 10;                 // tile never straddles q/k/v
    float* dst = (which == 0) ? g_q : (which == 1) ? g_k : g_v;
    const int bq = m0 >> 11;
    const int t0 = m0 & (T_DIM - 1);
    const int h  = (((n0 & 1023) + wn * 32) >> 6);  // constant per warp

    #pragma unroll
    for (int nt = 0; nt < 4; nt++) {
        const int ncol = wn * 32 + nt * 8 + 2 * (lane & 3);
        const float2 bias = *(const float2*)(b + n0 + ncol);
        const int d = ncol & 63;
        const size_t rowbase = (size_t)(bq * H_DIM + h) * T_DIM;
        #pragma unroll
        for (int mt = 0; mt < 4; mt++) {
            const int t = t0 + wm * 64 + mt * 16 + (lane >> 2);
            float2 v0 = { acc[mt][nt][0] + bias.x, acc[mt][nt][1] + bias.y };
            float2 v1 = { acc[mt][nt][2] + bias.x, acc[mt][nt][3] + bias.y };
            *(float2*)(dst + (rowbase + t) * HD + d)       = v0;
            *(float2*)(dst + (rowbase + t + 8) * HD + d)   = v1;
        }
    }
}

// ---------------------------------------------------------------------------
// Flash attention (TF32 tensor cores).
// CTA: 64 q-rows, 4 warps (16 rows each). KV tiles of 64.
// Online softmax fully in registers (quad shuffles).
// ---------------------------------------------------------------------------
#define KS_PAD 68   // bank = (4*row'+col')%32 for frag reads: conflict-free
#define VS_PAD 72   // bank = (8*row'+col')%32 for frag reads: conflict-free
#define SMEM_U32 (64 * KS_PAD + 64 * VS_PAD + 64 * KS_PAD)
#define ATTN_SMEM_BYTES (SMEM_U32 * 4)

__global__ __launch_bounds__(128) void attn_tf32(float* __restrict__ out)
{
    extern __shared__ uint32_t sm[];
    uint32_t (*Ks)[KS_PAD] = (uint32_t(*)[KS_PAD])(sm);
    uint32_t (*Vs)[VS_PAD] = (uint32_t(*)[VS_PAD])(sm + 64 * KS_PAD);
    uint32_t (*Ps)[KS_PAD] = (uint32_t(*)[KS_PAD])(sm + 64 * KS_PAD + 64 * VS_PAD);

    const int tid  = threadIdx.x;
    const int lane = tid & 31;
    const int warp = tid >> 5;
    const int qt = blockIdx.x;      // q tile 0..31
    const int bh = blockIdx.y;      // 0..63

    const size_t hoff = (size_t)bh * T_DIM * HD;
    const float* Qg = g_q + hoff;
    const float* Kg = g_k + hoff;
    const float* Vg = g_v + hoff;

    // Stage Q tile (scaled by 1/8) through Ps, then pull A-frags to registers.
    {
        const int row = tid >> 1;
        const int col = (tid & 1) * 32;
        const float* qp = Qg + (size_t)(qt * 64 + row) * HD + col;
        #pragma unroll
        for (int i = 0; i < 8; i++) {
            float4 v = *(const float4*)(qp + i * 4);
            Ps[row][col + i * 4 + 0] = f2tf(v.x * 0.125f);
            Ps[row][col + i * 4 + 1] = f2tf(v.y * 0.125f);
            Ps[row][col + i * 4 + 2] = f2tf(v.z * 0.125f);
            Ps[row][col + i * 4 + 3] = f2tf(v.w * 0.125f);
        }
    }
    __syncthreads();
    uint32_t qa[8][4];
    {
        const int r = warp * 16 + (lane >> 2);
        #pragma unroll
        for (int k = 0; k < 8; k++) {
            const int c = k * 8 + (lane & 3);
            qa[k][0] = Ps[r][c];     qa[k][1] = Ps[r + 8][c];
            qa[k][2] = Ps[r][c + 4]; qa[k][3] = Ps[r + 8][c + 4];
        }
    }

    float oa[8][4] = {};
    float mrow0 = -1e30f, mrow1 = -1e30f, l0 = 0.0f, l1 = 0.0f;
    const int gr0 = qt * 64 + warp * 16 + (lane >> 2);
    const int gr1 = gr0 + 8;

    for (int kt = 0; kt <= qt; kt++) {
        __syncthreads();  // Ks/Vs consumers from previous iter done, qa loads done
        {
            const int row = tid >> 1;
            const int col = (tid & 1) * 32;
            const float* kp = Kg + (size_t)(kt * 64 + row) * HD + col;
            const float* vp = Vg + (size_t)(kt * 64 + row) * HD + col;
            #pragma unroll
            for (int i = 0; i < 8; i++) {
                float4 kv = *(const float4*)(kp + i * 4);
                Ks[row][col + i * 4 + 0] = f2tf(kv.x);
                Ks[row][col + i * 4 + 1] = f2tf(kv.y);
                Ks[row][col + i * 4 + 2] = f2tf(kv.z);
                Ks[row][col + i * 4 + 3] = f2tf(kv.w);
                float4 vv = *(const float4*)(vp + i * 4);
                Vs[row][col + i * 4 + 0] = f2tf(vv.x);
                Vs[row][col + i * 4 + 1] = f2tf(vv.y);
                Vs[row][col + i * 4 + 2] = f2tf(vv.z);
                Vs[row][col + i * 4 + 3] = f2tf(vv.w);
            }
        }
        __syncthreads();

        // S = Q @ K^T
        float s[8][4] = {};
        #pragma unroll
        for (int k = 0; k < 8; k++) {
            #pragma unroll
            for (int j = 0; j < 8; j++) {
                uint32_t bfr[2];
                const int rr = j * 8 + (lane >> 2);
                const int cc = k * 8 + (lane & 3);
                bfr[0] = Ks[rr][cc];
                bfr[1] = Ks[rr][cc + 4];
                mma_tf32(s[j], qa[k], bfr);
            }
        }

        // Causal mask (diagonal tile only)
        if (kt == qt) {
            #pragma unroll
            for (int j = 0; j < 8; j++) {
                const int c0 = kt * 64 + j * 8 + 2 * (lane & 3);
                if (c0     > gr0) s[j][0] = -1e30f;
                if (c0 + 1 > gr0) s[j][1] = -1e30f;
                if (c0     > gr1) s[j][2] = -1e30f;
                if (c0 + 1 > gr1) s[j][3] = -1e30f;
            }
        }

        // Online softmax in registers (quad = lanes sharing lane>>2)
        float mx0 = -1e30f, mx1 = -1e30f;
        #pragma unroll
        for (int j = 0; j < 8; j++) {
            mx0 = fmaxf(mx0, fmaxf(s[j][0], s[j][1]));
            mx1 = fmaxf(mx1, fmaxf(s[j][2], s[j][3]));
        }
        mx0 = fmaxf(mx0, __shfl_xor_sync(0xffffffff, mx0, 1));
        mx0 = fmaxf(mx0, __shfl_xor_sync(0xffffffff, mx0, 2));
        mx1 = fmaxf(mx1, __shfl_xor_sync(0xffffffff, mx1, 1));
        mx1 = fmaxf(mx1, __shfl_xor_sync(0xffffffff, mx1, 2));

        const float nm0 = fmaxf(mrow0, mx0);
        const float nm1 = fmaxf(mrow1, mx1);
        const float corr0 = __expf(mrow0 - nm0);
        const float corr1 = __expf(mrow1 - nm1);
        mrow0 = nm0; mrow1 = nm1;

        float sum0 = 0.0f, sum1 = 0.0f;
        #pragma unroll
        for (int j = 0; j < 8; j++) {
            s[j][0] = __expf(s[j][0] - nm0); sum0 += s[j][0];
            s[j][1] = __expf(s[j][1] - nm0); sum0 += s[j][1];
            s[j][2] = __expf(s[j][2] - nm1); sum1 += s[j][2];
            s[j][3] = __expf(s[j][3] - nm1); sum1 += s[j][3];
        }
        sum0 += __shfl_xor_sync(0xffffffff, sum0, 1);
        sum0 += __shfl_xor_sync(0xffffffff, sum0, 2);
        sum1 += __shfl_xor_sync(0xffffffff, sum1, 1);
        sum1 += __shfl_xor_sync(0xffffffff, sum1, 2);
        l0 = l0 * corr0 + sum0;
        l1 = l1 * corr1 + sum1;

        #pragma unroll
        for (int j = 0; j < 8; j++) {
            oa[j][0] *= corr0; oa[j][1] *= corr0;
            oa[j][2] *= corr1; oa[j][3] *= corr1;
        }

        // Store P (warp-private rows of Ps)
        {
            const int r = warp * 16 + (lane >> 2);
            #pragma unroll
            for (int j = 0; j < 8; j++) {
                const int c = j * 8 + 2 * (lane & 3);
                Ps[r][c]         = f2tf(s[j][0]);
                Ps[r][c + 1]     = f2tf(s[j][1]);
                Ps[r + 8][c]     = f2tf(s[j][2]);
                Ps[r + 8][c + 1] = f2tf(s[j][3]);
            }
        }
        __syncwarp();

        // O += P @ V
        #pragma unroll
        for (int k2 = 0; k2 < 8; k2++) {
            uint32_t af[4];
            const int r = warp * 16 + (lane >> 2);
            const int c = k2 * 8 + (lane & 3);
            af[0] = Ps[r][c];     af[1] = Ps[r + 8][c];
            af[2] = Ps[r][c + 4]; af[3] = Ps[r + 8][c + 4];
            #pragma unroll
            for (int j = 0; j < 8; j++) {
                uint32_t bfr[2];
                const int vr = k2 * 8 + (lane & 3);
                const int vc = j * 8 + (lane >> 2);
                bfr[0] = Vs[vr][vc];
                bfr[1] = Vs[vr + 4][vc];
                mma_tf32(oa[j], af, bfr);
            }
        }
    }

    // Epilogue: normalize and write [B,T,C]
    const float inv0 = 1.0f / l0;
    const float inv1 = 1.0f / l1;
    const int bq = bh >> 4;
    const int h  = bh & 15;
    const int trow = qt * 64 + warp * 16 + (lane >> 2);
    #pragma unroll
    for (int j = 0; j < 8; j++) {
        const int d = j * 8 + 2 * (lane & 3);
        float2 v0 = { oa[j][0] * inv0, oa[j][1] * inv0 };
        float2 v1 = { oa[j][2] * inv1, oa[j][3] * inv1 };
        *(float2*)(out + (size_t)(bq * T_DIM + trow) * C_DIM + h * HD + d)     = v0;
        *(float2*)(out + (size_t)(bq * T_DIM + trow + 8) * C_DIM + h * HD + d) = v1;
    }
}

// ---------------------------------------------------------------------------
extern "C" void kernel_launch(void* const* d_in, const int* in_sizes, int n_in,
                              void* d_out, int out_size)
{
    const float* x = (const float*)d_in[0];   // [4, 2048, 1024]
    const float* W = (const float*)d_in[1];   // [3072, 1024]
    const float* b = (const float*)d_in[2];   // [3072]
    float* out = (float*)d_out;               // [4, 2048, 1024]

    cudaFuncSetAttribute(attn_tf32, cudaFuncAttributeMaxDynamicSharedMemorySize,
                         ATTN_SMEM_BYTES);

    qkv_gemm_tf32<<<dim3(N_TOT / 128, M_TOT / 128), 256>>>(x, W, b);
    attn_tf32<<<dim3(T_DIM / 64, B_DIM * H_DIM), 128, ATTN_SMEM_BYTES>>>(out);
}